// round 17
// baseline (speedup 1.0000x reference)
#include <cuda_runtime.h>
#include <cuda_fp16.h>
#include <cstdint>

typedef unsigned long long ull;

#define VOCAB 50257
#define NT 512
#define NW 16                    // warps per CTA
#define NPAIR 25128              // float2 pairs per row after 1-element peel
#define NPJ 49                   // full pair iterations: 49*512 = 25088
#define TAILP 40                 // tail pairs
#define T1 6.0f                  // capture threshold; E[count(g>=6)] ~ 205, k-th ~ 7.4
#define CAP 768                  // candidate buffer capacity (mean 205, sigma ~14)
#define WMAX 128                 // fallback bisection window
#define ESM_BYTES (NPAIR * 4)    // fp16x2 e-values: 100512 B

struct Scratch {
    int   sredi[NW + 1];
    float sredf[NW + 1];
    float cbuf[CAP];
    float wbuf[WMAX + 32];
    int   ccnt;
    int   wcnt;
    float thrslot;
    float gscalar;               // peeled scalar element, exact fp32
    float lscalar;
    float escalar;
};

#define SMEM_TOTAL (ESM_BYTES + (int)sizeof(Scratch))

// ---- packed f32x2 helpers ----
__device__ __forceinline__ ull pk(float x, float y) {
    ull r; asm("mov.b64 %0, {%1, %2};" : "=l"(r) : "f"(x), "f"(y)); return r;
}
__device__ __forceinline__ void upk(ull v, float& x, float& y) {
    asm("mov.b64 {%0, %1}, %2;" : "=f"(x), "=f"(y) : "l"(v));
}
#define F2FMA(d, a, b, c) asm("fma.rn.f32x2 %0, %1, %2, %3;" : "=l"(d) : "l"(a), "l"(b), "l"(c))
#define F2ADD(d, a, b)    asm("add.rn.f32x2 %0, %1, %2;"     : "=l"(d) : "l"(a), "l"(b))
#define F2MUL(d, a, b)    asm("mul.rn.f32x2 %0, %1, %2;"     : "=l"(d) : "l"(a), "l"(b))

__device__ __forceinline__ float lg2f(float x) { float r; asm("lg2.approx.f32 %0, %1;" : "=f"(r) : "f"(x)); return r; }
__device__ __forceinline__ float ex2f(float x) { float r; asm("ex2.approx.f32 %0, %1;" : "=f"(r) : "f"(x)); return r; }
__device__ __forceinline__ float rcpf(float x) { float r; asm("rcp.approx.f32 %0, %1;" : "=f"(r) : "f"(x)); return r; }

// ---- order-preserving float <-> u32 key (fallback path only) ----
__device__ __forceinline__ unsigned fkey(float f) {
    unsigned b = __float_as_uint(f);
    unsigned m = (unsigned)(((int)b) >> 31) | 0x80000000u;
    return b ^ m;
}
__device__ __forceinline__ float keyf(unsigned k) {
    unsigned m = (~(unsigned)(((int)k) >> 31)) | 0x80000000u;
    return __uint_as_float(k ^ m);
}

// ---- block reductions (512 threads = 16 warps) ----
__device__ __forceinline__ int blockSumI(int v, int* s) {
    #pragma unroll
    for (int o = 16; o; o >>= 1) v += __shfl_xor_sync(0xffffffffu, v, o);
    int wid = threadIdx.x >> 5, lane = threadIdx.x & 31;
    if (lane == 0) s[wid] = v;
    __syncthreads();
    if (wid == 0) {
        int x = (lane < NW) ? s[lane] : 0;
        #pragma unroll
        for (int o = 8; o; o >>= 1) x += __shfl_xor_sync(0xffffffffu, x, o);
        if (lane == 0) s[NW] = x;
    }
    __syncthreads();
    int r = s[NW];
    __syncthreads();
    return r;
}

__device__ __forceinline__ float blockSumF(float v, float* s) {
    #pragma unroll
    for (int o = 16; o; o >>= 1) v += __shfl_xor_sync(0xffffffffu, v, o);
    int wid = threadIdx.x >> 5, lane = threadIdx.x & 31;
    if (lane == 0) s[wid] = v;
    __syncthreads();
    if (wid == 0) {
        float x = (lane < NW) ? s[lane] : 0.0f;
        #pragma unroll
        for (int o = 8; o; o >>= 1) x += __shfl_xor_sync(0xffffffffu, x, o);
        if (lane == 0) s[NW] = x;
    }
    __syncthreads();
    float r = s[NW];
    __syncthreads();
    return r;
}

// scalar gumbel noise (peeled element only); exact log1p polynomial for u near 1
__device__ __forceinline__ float gumbel_noise(float uu) {
    float vlog = -__logf(uu + 1e-10f);
    float d = uu - 1.0f;                         // exact (Sterbenz) for uu in [0.5, 2)
    float p = __fmaf_rn(-0.25f, d, 0.33333333f);
    p = __fmaf_rn(p, d, -0.5f);
    p = __fmaf_rn(p, d, 1.0f);
    float vpoly = -(d * p);
    float v = (uu > 0.99f) ? vpoly : vlog;
    return -__logf(v + 1e-10f);
}

__device__ __forceinline__ void cap_push(float g, Scratch* sc) {
    if (g >= T1) {
        int p = atomicAdd(&sc->ccnt, 1);
        if (p < CAP) sc->cbuf[p] = g;
    }
}

// packed-pair gumbel: g = l + noise(u). Bitwise-deterministic (explicit asm ops)
// so the P3 recompute reproduces P1's g exactly.
struct GC { ull eps2, nln2, none2, c025, cm13, cp05; };
__device__ __forceinline__ ull gumbel_pair(float2 uv, ull Lp, const GC& c) {
    ull U = pk(uv.x, uv.y);
    ull T; F2ADD(T, U, c.eps2);                  // u + eps
    float tx, ty; upk(T, tx, ty);
    ull LGU = pk(lg2f(tx), lg2f(ty));
    ull VL; F2MUL(VL, LGU, c.nln2);              // vlog = -ln(u+eps)
    ull D; F2ADD(D, U, c.none2);                 // d = u - 1 (exact)
    ull Q; F2FMA(Q, c.c025, D, c.cm13);
    F2FMA(Q, Q, D, c.cp05);
    F2FMA(Q, Q, D, c.none2);
    ull VP; F2MUL(VP, D, Q);                     // vpoly (exact log1p path near u=1)
    float vpx, vpy, vlx, vly;
    upk(VP, vpx, vpy);
    upk(VL, vlx, vly);
    float vx = (uv.x > 0.99f) ? vpx : vlx;
    float vy = (uv.y > 0.99f) ? vpy : vly;
    ull LGV = pk(lg2f(vx + 1e-10f), lg2f(vy + 1e-10f));
    ull G; F2FMA(G, LGV, c.nln2, Lp);            // g = l - ln2*lg2(v+eps)
    return G;
}

// packed-pair mask+exp: e = exp(l * sigmoid(g - thr)).
struct PC { ull nl2e, thr2, one2, l2e2; };
__device__ __forceinline__ ull p3_pair(ull G, ull Lp, const PC& c) {
    ull T; F2FMA(T, G, c.nl2e, c.thr2);          // (thr - g) * log2e
    float tx, ty; upk(T, tx, ty);
    ull Z = pk(ex2f(tx), ex2f(ty));
    ull W; F2ADD(W, Z, c.one2);
    float wx, wy; upk(W, wx, wy);
    ull S = pk(rcpf(wx), rcpf(wy));              // sigmoid
    ull M; F2MUL(M, Lp, S);
    F2MUL(M, M, c.l2e2);
    float mx, my; upk(M, mx, my);
    return pk(ex2f(mx), ex2f(my));
}

__global__ void __launch_bounds__(NT, 2)
gumbel_sampler_kernel(const float* __restrict__ logits,
                      const float* __restrict__ uin,
                      const int* __restrict__ kp,
                      float* __restrict__ out)
{
    extern __shared__ unsigned char smem_raw[];
    __half2* esm = (__half2*)smem_raw;           // fp16x2 e-values (pass C input)
    Scratch* sc  = (Scratch*)(smem_raw + ESM_BYTES);

    const int row = blockIdx.x;
    const int tid = threadIdx.x;
    const int p   = row & 1;                    // peel count for 8B alignment
    const int esc = p ? 0 : (VOCAB - 1);        // global index of the scalar element
    const float* __restrict__ lrow = logits + (size_t)row * VOCAB;
    const float* __restrict__ urow = uin    + (size_t)row * VOCAB;
    float* __restrict__ orow = out + (size_t)row * VOCAB;
    const float2* __restrict__ l2 = (const float2*)(lrow + p);
    const float2* __restrict__ u2 = (const float2*)(urow + p);
    float2* __restrict__ o2 = (float2*)(orow + p);

    if (tid == 0) sc->ccnt = 0;
    __syncthreads();

    const GC gc = { pk(1e-10f, 1e-10f), pk(-0.69314718056f, -0.69314718056f),
                    pk(-1.0f, -1.0f),   pk(0.25f, 0.25f),
                    pk(-0.33333333f, -0.33333333f), pk(0.5f, 0.5f) };

    // ------- P1: load + gumbel; ONLY candidates are kept (no g state!) -------
    // Default-policy loads: lines stay in L2 for the P3 re-read (~15us later).
    // No register arrays anywhere -> partial unroll is safe (cf. R3 post-mortem).
    #pragma unroll 4
    for (int j = 0; j < NPJ; ++j) {
        int t = tid + j * NT;
        float2 lv = l2[t];
        float2 uv = u2[t];
        ull G = gumbel_pair(uv, pk(lv.x, lv.y), gc);
        float gx, gy; upk(G, gx, gy);
        cap_push(gx, sc);
        cap_push(gy, sc);
    }
    if (tid < TAILP) {
        int t = NPJ * NT + tid;
        float2 lv = l2[t];
        float2 uv = u2[t];
        ull G = gumbel_pair(uv, pk(lv.x, lv.y), gc);
        float gx, gy; upk(G, gx, gy);
        cap_push(gx, sc);
        cap_push(gy, sc);
    }
    if (tid == 0) {   // peeled scalar element (state kept in Scratch)
        float l = lrow[esc];
        float g = l + gumbel_noise(urow[esc]);
        sc->gscalar = g;
        sc->lscalar = l;
        cap_push(g, sc);
    }
    __syncthreads();

    // ------- P2: exact k-th largest from the candidate buffer -------
    // count(>=T1) = m >= k  =>  k-th largest overall is the k-th largest of cbuf.
    const int k = *kp;
    int m = sc->ccnt;
    float thr;

    if (m >= k && m <= CAP) {
        // up to 2 candidates per thread (m can exceed NT)
        float vt0 = (tid      < m) ? sc->cbuf[tid]      : 0.0f;
        float vt1 = (tid + NT < m) ? sc->cbuf[tid + NT] : 0.0f;
        int gt0 = 0, ge0 = 0, gt1 = 0, ge1 = 0;
        for (int j = 0; j < m; ++j) {
            float vj = sc->cbuf[j];              // broadcast LDS
            gt0 += (vj >  vt0); ge0 += (vj >= vt0);
            gt1 += (vj >  vt1); ge1 += (vj >= vt1);
        }
        if (tid      < m && gt0 < k && k <= ge0) sc->thrslot = vt0;
        if (tid + NT < m && gt1 < k && k <= ge1) sc->thrslot = vt1;
        __syncthreads();
        thr = sc->thrslot;
    } else {
        // fallback (never expected): bisection with full recompute of g.
        unsigned lo = 0u, hi = 0xFFFFFFFFu;
        int c_lo = VOCAB, c_hi = 0;
        while ((hi - lo) > 1u && (c_lo - c_hi) > WMAX) {
            unsigned mid = lo + ((hi - lo) >> 1);
            int c = 0;
            for (int t = tid; t < NPAIR; t += NT) {
                float2 lv = l2[t];
                float2 uv = u2[t];
                ull G = gumbel_pair(uv, pk(lv.x, lv.y), gc);
                float gx, gy; upk(G, gx, gy);
                c += (fkey(gx) >= mid) + (fkey(gy) >= mid);
            }
            if (tid == 0) c += (fkey(sc->gscalar) >= mid);
            c = blockSumI(c, sc->sredi);
            if (c >= k) { lo = mid; c_lo = c; }
            else        { hi = mid; c_hi = c; }
        }
        if ((hi - lo) <= 1u) {
            thr = keyf(lo);
        } else {
            if (tid == 0) sc->wcnt = 0;
            __syncthreads();
            for (int t = tid; t < NPAIR; t += NT) {
                float2 lv = l2[t];
                float2 uv = u2[t];
                ull G = gumbel_pair(uv, pk(lv.x, lv.y), gc);
                float gg[2]; upk(G, gg[0], gg[1]);
                #pragma unroll
                for (int h = 0; h < 2; ++h) {
                    unsigned kk = fkey(gg[h]);
                    if (kk >= lo && kk < hi) {
                        int pq = atomicAdd(&sc->wcnt, 1);
                        if (pq < WMAX + 32) sc->wbuf[pq] = gg[h];
                    }
                }
            }
            if (tid == 0) {
                unsigned ks = fkey(sc->gscalar);
                if (ks >= lo && ks < hi) {
                    int pq = atomicAdd(&sc->wcnt, 1);
                    if (pq < WMAX + 32) sc->wbuf[pq] = sc->gscalar;
                }
            }
            __syncthreads();
            int w = sc->wcnt; if (w > WMAX + 32) w = WMAX + 32;
            int need = k - c_hi;
            if (tid < w) {
                float vt = sc->wbuf[tid];
                int gt = 0, ge = 0;
                for (int j = 0; j < w; ++j) {
                    float vj = sc->wbuf[j];
                    gt += (vj >  vt);
                    ge += (vj >= vt);
                }
                if (gt < need && need <= ge) sc->thrslot = vt;
            }
            __syncthreads();
            thr = sc->thrslot;
        }
    }

    // ------- P3: re-read l,u; recompute g (bitwise-identical); e -> fp16 smem ----
    // masked = l * sigmoid(g - thr), |masked| <= ~5.5 -> exp in [e^-6, e^6]:
    // no-max softmax is exact; fp16 e-storage adds <= 2^-11 relative error.
    const float L2E = 1.4426950408889634f;
    const PC pc = { pk(-L2E, -L2E), pk(thr * L2E, thr * L2E),
                    pk(1.0f, 1.0f), pk(L2E, L2E) };
    ull acc = pk(0.0f, 0.0f);
    #pragma unroll 2
    for (int j = 0; j < NPJ; ++j) {
        int t = tid + j * NT;
        float2 lv = __ldcs(l2 + t);              // last use: evict-first
        float2 uv = __ldcs(u2 + t);
        ull Lp = pk(lv.x, lv.y);
        ull G = gumbel_pair(uv, Lp, gc);
        ull E = p3_pair(G, Lp, pc);
        F2ADD(acc, acc, E);
        float ex, ey; upk(E, ex, ey);
        esm[t] = __floats2half2_rn(ex, ey);
    }
    if (tid < TAILP) {
        int t = NPJ * NT + tid;
        float2 lv = __ldcs(l2 + t);
        float2 uv = __ldcs(u2 + t);
        ull Lp = pk(lv.x, lv.y);
        ull G = gumbel_pair(uv, Lp, gc);
        ull E = p3_pair(G, Lp, pc);
        F2ADD(acc, acc, E);
        float ex, ey; upk(E, ex, ey);
        esm[t] = __floats2half2_rn(ex, ey);
    }
    float ax, ay; upk(acc, ax, ay);
    float lsum = ax + ay;
    if (tid == 0) {
        float s = __fdividef(1.0f, 1.0f + __expf(thr - sc->gscalar));
        float e = __expf(sc->lscalar * s);
        sc->escalar = e;
        lsum += e;
    }
    float S = blockSumF(lsum, sc->sredf);
    float inv = __fdividef(1.0f, S);

    // ------- Pass C: scale fp16 e-values and stream out -------
    #pragma unroll 4
    for (int j = 0; j < NPJ; ++j) {
        int t = tid + j * NT;
        float2 e = __half22float2(esm[t]);
        __stcs(o2 + t, make_float2(e.x * inv, e.y * inv));
    }
    if (tid < TAILP) {
        int t = NPJ * NT + tid;
        float2 e = __half22float2(esm[t]);
        __stcs(o2 + t, make_float2(e.x * inv, e.y * inv));
    }
    if (tid == 0) {
        __stcs(orow + esc, sc->escalar * inv);
    }
}

extern "C" void kernel_launch(void* const* d_in, const int* in_sizes, int n_in,
                              void* d_out, int out_size)
{
    const float* logits = (const float*)d_in[0];
    const float* u      = (const float*)d_in[1];
    const int*   kp     = (const int*)d_in[2];
    float* out = (float*)d_out;

    int B = out_size / VOCAB;

    cudaFuncSetAttribute(gumbel_sampler_kernel,
                         cudaFuncAttributeMaxDynamicSharedMemorySize, SMEM_TOTAL);
    gumbel_sampler_kernel<<<B, NT, SMEM_TOTAL>>>(logits, u, kp, out);
}